// round 11
// baseline (speedup 1.0000x reference)
#include <cuda_runtime.h>
#include <cuda_fp16.h>
#include <cstdint>

#define B_DIM 8
#define T_DIM 4096
#define C_DIM 1024
#define M_DIM (B_DIM * T_DIM)   // 32768
#define N_DIM (2 * C_DIM)       // 2048
#define KX    2048              // x storage: [hi 1024 | lo 1024]
#define KW    1024              // W storage: hi only

// Static scratch (no allocs allowed)
__device__ float  g_pg[(size_t)M_DIM * N_DIM];   // 256 MB: [p | gate logits]
__device__ __half g_xs[(size_t)M_DIM * KX];      // 128 MB: x split hi/lo (fp16)
__device__ __half g_ws[(size_t)N_DIM * KW];      //   4 MB: [Ws;Wg] hi (fp16)

// ---------------------------------------------------------------------------
// Baseline-PTX helpers (plain sm_103 target: no tcgen05/TMEM/'a' features)
// ---------------------------------------------------------------------------
__device__ __forceinline__ uint32_t smem_u32(const void* p) {
    uint32_t a;
    asm("{ .reg .u64 t; cvta.to.shared.u64 t, %1; cvt.u32.u64 %0, t; }" : "=r"(a) : "l"(p));
    return a;
}
#define CP_ASYNC16(dst, src) \
    asm volatile("cp.async.cg.shared.global [%0], [%1], 16;" :: "r"(dst), "l"(src))
#define CP_COMMIT() asm volatile("cp.async.commit_group;" ::: "memory")
#define CP_WAIT(n)  asm volatile("cp.async.wait_group %0;" :: "n"(n) : "memory")

__device__ __forceinline__ uint32_t sw128(uint32_t off) { return off ^ ((off >> 3) & 0x70); }

__device__ __forceinline__ void ldsm_x4(uint32_t r[4], uint32_t addr) {
    asm volatile("ldmatrix.sync.aligned.m8n8.x4.shared.b16 {%0,%1,%2,%3}, [%4];"
                 : "=r"(r[0]), "=r"(r[1]), "=r"(r[2]), "=r"(r[3]) : "r"(addr));
}
__device__ __forceinline__ void mma16816(float c[4], const uint32_t a[4],
                                         uint32_t b0, uint32_t b1) {
    asm volatile("mma.sync.aligned.m16n8k16.row.col.f32.f16.f16.f32 "
                 "{%0,%1,%2,%3}, {%4,%5,%6,%7}, {%8,%9}, {%0,%1,%2,%3};"
                 : "+f"(c[0]), "+f"(c[1]), "+f"(c[2]), "+f"(c[3])
                 : "r"(a[0]), "r"(a[1]), "r"(a[2]), "r"(a[3]), "r"(b0), "r"(b1));
}

// ---------------------------------------------------------------------------
// Split converters
// ---------------------------------------------------------------------------
__global__ __launch_bounds__(256) void split_x(const float* __restrict__ x) {
    size_t i = (size_t)blockIdx.x * 256 + threadIdx.x;   // one float4 per thread
    size_t m = i >> 8;                                    // 256 float4 per row
    int    c4 = (int)(i & 255);
    float4 v = ((const float4*)x)[i];
    __half h[4], l[4];
    float f[4] = {v.x, v.y, v.z, v.w};
    #pragma unroll
    for (int j = 0; j < 4; ++j) {
        h[j] = __float2half_rn(f[j]);
        l[j] = __float2half_rn(f[j] - __half2float(h[j]));
    }
    __half* row = g_xs + m * KX;
    *(uint2*)(row + c4 * 4)        = *(uint2*)h;
    *(uint2*)(row + 1024 + c4 * 4) = *(uint2*)l;
}

__global__ __launch_bounds__(256) void split_w(const float* __restrict__ Ws,
                                               const float* __restrict__ Wg) {
    size_t i = (size_t)blockIdx.x * 256 + threadIdx.x;   // one float4 per thread
    size_t n = i >> 8;
    int    c4 = (int)(i & 255);
    const float* src = (n < 1024) ? (Ws + n * 1024) : (Wg + (n - 1024) * 1024);
    float4 v = ((const float4*)(src))[c4];
    __half h[4];
    h[0] = __float2half_rn(v.x); h[1] = __float2half_rn(v.y);
    h[2] = __float2half_rn(v.z); h[3] = __float2half_rn(v.w);
    *(uint2*)(g_ws + n * KW + c4 * 4) = *(uint2*)h;
}

// ---------------------------------------------------------------------------
// HMMA GEMM: pg[m,n] = sum_k x[m,k] W[n,k] + bias[n]
// fp16 2-segment schedule: x_hi.W_hi + x_lo.W_hi  (K_eff = 2048)
// CTA 128x128, BK=64, 3-stage cp.async, 8 warps (4Mx2N), warp tile 32x64.
// ---------------------------------------------------------------------------
#define NSTAGE 3
#define A_BYTES 16384                 // 128 rows x 128B (64 fp16)
#define B_BYTES 16384
#define STAGE_BYTES (A_BYTES + B_BYTES)
#define SMEM_TOTAL (NSTAGE * STAGE_BYTES)   // 98304
#define KITERS 32                      // 2 segments x 16 chunks of 64

__global__ __launch_bounds__(256, 2) void tc_gemm(const float* __restrict__ bsv,
                                                  const float* __restrict__ bgv) {
    extern __shared__ char smem[];
    const uint32_t sbase = smem_u32(smem);
    const int tid  = threadIdx.x;
    const int wid  = tid >> 5, lane = tid & 31;
    const int wm   = wid >> 1;           // 0..3 -> M offset wm*32
    const int wn   = wid & 1;            // 0..1 -> N offset wn*64
    const int ntile = blockIdx.x;        // 0..15
    const int mtile = blockIdx.y;        // 0..255

    const __half* Abase = g_xs + (size_t)mtile * 128 * KX;
    const __half* Bbase = g_ws + (size_t)ntile * 128 * KW;

    float acc[2][8][4];
    #pragma unroll
    for (int g = 0; g < 2; ++g)
        #pragma unroll
        for (int j = 0; j < 8; ++j)
            #pragma unroll
            for (int q = 0; q < 4; ++q) acc[g][j][q] = 0.0f;

    auto issue_loads = [&](int it, int buf) {
        const int kk   = (it & 15) * 64;
        const int acol = ((it >> 4) ? 1024 : 0) + kk;   // seg1 reads x_lo
        const uint32_t sb = sbase + buf * STAGE_BYTES;
        #pragma unroll
        for (int i = 0; i < 4; ++i) {                 // A: 1024 16B-chunks / 256 thr
            int q = tid + i * 256;
            int row = q >> 3, c = q & 7;
            CP_ASYNC16(sb + sw128(row * 128 + c * 16),
                       Abase + (size_t)row * KX + acol + c * 8);
        }
        #pragma unroll
        for (int i = 0; i < 4; ++i) {                 // B: 1024 chunks (W_hi only)
            int q = tid + i * 256;
            int row = q >> 3, c = q & 7;
            CP_ASYNC16(sb + A_BYTES + sw128(row * 128 + c * 16),
                       Bbase + (size_t)row * KW + kk + c * 8);
        }
    };

    issue_loads(0, 0); CP_COMMIT();
    issue_loads(1, 1); CP_COMMIT();

    const uint32_t arow  = (uint32_t)(wm * 32 + (lane & 15)) * 128;
    const uint32_t brow  = (uint32_t)(wn * 64 + (lane & 15)) * 128;
    const uint32_t khalf = ((lane >> 4) & 1) * 16;

    int buf = 0;
    for (int it = 0; it < KITERS; ++it) {
        CP_WAIT(1);
        __syncthreads();
        const int nbuf = (buf + 2 >= NSTAGE) ? buf + 2 - NSTAGE : buf + 2;
        if (it + 2 < KITERS) issue_loads(it + 2, nbuf);
        CP_COMMIT();

        const uint32_t sA = sbase + buf * STAGE_BYTES;
        const uint32_t sB = sA + A_BYTES;

        #pragma unroll
        for (int ks = 0; ks < 4; ++ks) {
            const uint32_t kb = ks * 32 + khalf;
            uint32_t a0[4], a1[4];
            ldsm_x4(a0, sA + sw128(arow + kb));
            ldsm_x4(a1, sA + sw128(arow + 2048 + kb));    // +16 rows
            uint32_t b[4][4];
            #pragma unroll
            for (int q = 0; q < 4; ++q)
                ldsm_x4(b[q], sB + sw128(brow + q * 2048 + kb));
            #pragma unroll
            for (int q = 0; q < 4; ++q) {
                mma16816(acc[0][2 * q + 0], a0, b[q][0], b[q][2]);
                mma16816(acc[0][2 * q + 1], a0, b[q][1], b[q][3]);
                mma16816(acc[1][2 * q + 0], a1, b[q][0], b[q][2]);
                mma16816(acc[1][2 * q + 1], a1, b[q][1], b[q][3]);
            }
        }
        buf = (buf + 1 >= NSTAGE) ? 0 : buf + 1;
    }

    // Epilogue: bias + store fp32 to g_pg
    const int m0 = mtile * 128 + wm * 32 + (lane >> 2);
    const int n0 = ntile * 128 + wn * 64 + 2 * (lane & 3);
    const float* bias = (ntile < 8) ? bsv : bgv;
    const int nb = (ntile < 8) ? n0 : n0 - 1024;

    #pragma unroll
    for (int j = 0; j < 8; ++j) {
        const int col = n0 + j * 8;
        const float bx = __ldg(bias + (nb + j * 8));
        const float by = __ldg(bias + (nb + j * 8) + 1);
        #pragma unroll
        for (int g = 0; g < 2; ++g) {
            const size_t r0 = (size_t)(m0 + g * 16);
            float2 v0 = {acc[g][j][0] + bx, acc[g][j][1] + by};
            float2 v1 = {acc[g][j][2] + bx, acc[g][j][3] + by};
            *(float2*)(g_pg + r0 * N_DIM + col)       = v0;
            *(float2*)(g_pg + (r0 + 8) * N_DIM + col) = v1;
        }
    }
}

// ---------------------------------------------------------------------------
// Sequential scan: s = tanh(p_t + s); out = sigmoid(z_t) * s  (accurate MUFU)
// ---------------------------------------------------------------------------
__device__ __forceinline__ float fast_ex2(float x) {
    float y; asm("ex2.approx.f32 %0, %1;" : "=f"(y) : "f"(x)); return y;
}
__device__ __forceinline__ float fast_rcp(float x) {
    float y; asm("rcp.approx.f32 %0, %1;" : "=f"(y) : "f"(x)); return y;
}

__global__ __launch_bounds__(128) void scan_kernel(float* __restrict__ out,
                                                   float* __restrict__ finals) {
    const int gid = blockIdx.x * blockDim.x + threadIdx.x;  // 0..8191
    const int b = gid >> 10;
    const int c = gid & (C_DIM - 1);

    const float* pp = g_pg + (size_t)b * T_DIM * N_DIM + c;
    float*       op = out  + (size_t)b * T_DIM * C_DIM + c;

    const float L2E  = 1.4426950408889634f;
    const float L2E2 = 2.8853900817779268f;
    float s = 0.0f;

    #pragma unroll 4
    for (int t = 0; t < T_DIM; ++t) {
        float p  = __ldcs(pp);
        float zg = __ldcs(pp + C_DIM);
        float gate = fast_rcp(1.0f + fast_ex2(-zg * L2E));
        float E = fast_ex2(fmaf(s, L2E2, p * L2E2));
        float r = fast_rcp(1.0f + E);
        s = fmaf(-2.0f, r, 1.0f);
        __stcs(op, gate * s);
        pp += N_DIM;
        op += C_DIM;
    }
    if (finals) finals[gid] = s;
}

// ---------------------------------------------------------------------------
extern "C" void kernel_launch(void* const* d_in, const int* in_sizes, int n_in,
                              void* d_out, int out_size) {
    const float* x  = (const float*)d_in[0];
    const float* Ws = (const float*)d_in[1];
    const float* bs = (const float*)d_in[2];
    const float* Wg = (const float*)d_in[3];
    const float* bg = (const float*)d_in[4];
    float* out = (float*)d_out;

    const size_t btc = (size_t)M_DIM * C_DIM;
    float* finals = ((size_t)out_size >= btc + (size_t)B_DIM * C_DIM)
                        ? out + btc : nullptr;

    cudaFuncSetAttribute(tc_gemm, cudaFuncAttributeMaxDynamicSharedMemorySize,
                         SMEM_TOTAL);

    split_x<<<(M_DIM * C_DIM / 4) / 256, 256>>>(x);
    split_w<<<(N_DIM * C_DIM / 4) / 256, 256>>>(Ws, Wg);
    tc_gemm<<<dim3(16, 256), 256, SMEM_TOTAL>>>(bs, bg);
    scan_kernel<<<B_DIM * C_DIM / 128, 128>>>(out, finals);
}

// round 12
// speedup vs baseline: 2.9125x; 2.9125x over previous
#include <cuda_runtime.h>
#include <cuda_fp16.h>
#include <cstdint>

#define B_DIM 8
#define T_DIM 4096
#define C_DIM 1024
#define M_DIM (B_DIM * T_DIM)   // 32768
#define N_DIM (2 * C_DIM)       // 2048
#define KX    2048              // x storage: [hi 1024 | lo 1024]
#define KW    1024              // W storage: hi only

// Static scratch (no allocs allowed)
__device__ float  g_pg[(size_t)M_DIM * N_DIM];   // 256 MB: [p | gate logits]
__device__ __half g_xs[(size_t)M_DIM * KX];      // 128 MB: x split hi/lo (fp16)
__device__ __half g_ws[(size_t)N_DIM * KW];      //   4 MB: [Ws;Wg] hi (fp16)

// ---------------------------------------------------------------------------
// Baseline-PTX helpers (plain sm_103 target: no tcgen05/TMEM/'a' features)
// ---------------------------------------------------------------------------
__device__ __forceinline__ uint32_t smem_u32(const void* p) {
    uint32_t a;
    asm("{ .reg .u64 t; cvta.to.shared.u64 t, %1; cvt.u32.u64 %0, t; }" : "=r"(a) : "l"(p));
    return a;
}
#define CP_ASYNC16(dst, src) \
    asm volatile("cp.async.cg.shared.global [%0], [%1], 16;" :: "r"(dst), "l"(src))
#define CP_COMMIT() asm volatile("cp.async.commit_group;" ::: "memory")
#define CP_WAIT(n)  asm volatile("cp.async.wait_group %0;" :: "n"(n) : "memory")

__device__ __forceinline__ uint32_t sw128(uint32_t off) { return off ^ ((off >> 3) & 0x70); }

__device__ __forceinline__ void ldsm_x4(uint32_t r[4], uint32_t addr) {
    asm volatile("ldmatrix.sync.aligned.m8n8.x4.shared.b16 {%0,%1,%2,%3}, [%4];"
                 : "=r"(r[0]), "=r"(r[1]), "=r"(r[2]), "=r"(r[3]) : "r"(addr));
}
__device__ __forceinline__ void mma16816(float c[4], const uint32_t a[4],
                                         uint32_t b0, uint32_t b1) {
    asm volatile("mma.sync.aligned.m16n8k16.row.col.f32.f16.f16.f32 "
                 "{%0,%1,%2,%3}, {%4,%5,%6,%7}, {%8,%9}, {%0,%1,%2,%3};"
                 : "+f"(c[0]), "+f"(c[1]), "+f"(c[2]), "+f"(c[3])
                 : "r"(a[0]), "r"(a[1]), "r"(a[2]), "r"(a[3]), "r"(b0), "r"(b1));
}

// ---------------------------------------------------------------------------
// Split converters
// ---------------------------------------------------------------------------
__global__ __launch_bounds__(256) void split_x(const float* __restrict__ x) {
    size_t i = (size_t)blockIdx.x * 256 + threadIdx.x;   // one float4 per thread
    size_t m = i >> 8;                                    // 256 float4 per row
    int    c4 = (int)(i & 255);
    float4 v = ((const float4*)x)[i];
    __half h[4], l[4];
    float f[4] = {v.x, v.y, v.z, v.w};
    #pragma unroll
    for (int j = 0; j < 4; ++j) {
        h[j] = __float2half_rn(f[j]);
        l[j] = __float2half_rn(f[j] - __half2float(h[j]));
    }
    __half* row = g_xs + m * KX;
    *(uint2*)(row + c4 * 4)        = *(uint2*)h;
    *(uint2*)(row + 1024 + c4 * 4) = *(uint2*)l;
}

__global__ __launch_bounds__(256) void split_w(const float* __restrict__ Ws,
                                               const float* __restrict__ Wg) {
    size_t i = (size_t)blockIdx.x * 256 + threadIdx.x;   // one float4 per thread
    size_t n = i >> 8;
    int    c4 = (int)(i & 255);
    const float* src = (n < 1024) ? (Ws + n * 1024) : (Wg + (n - 1024) * 1024);
    float4 v = ((const float4*)(src))[c4];
    __half h[4];
    h[0] = __float2half_rn(v.x); h[1] = __float2half_rn(v.y);
    h[2] = __float2half_rn(v.z); h[3] = __float2half_rn(v.w);
    *(uint2*)(g_ws + n * KW + c4 * 4) = *(uint2*)h;
}

// ---------------------------------------------------------------------------
// HMMA GEMM: pg[m,n] = sum_k x[m,k] W[n,k] + bias[n]
// fp16 2-segment schedule: x_hi.W_hi + x_lo.W_hi  (K_eff = 2048)
// CTA 128x128, BK=64, 3-stage cp.async, 8 warps (4Mx2N), warp tile 32x64.
// ---------------------------------------------------------------------------
#define NSTAGE 3
#define A_BYTES 16384                 // 128 rows x 128B (64 fp16)
#define B_BYTES 16384
#define STAGE_BYTES (A_BYTES + B_BYTES)
#define SMEM_TOTAL (NSTAGE * STAGE_BYTES)   // 98304
#define KITERS 32                      // 2 segments x 16 chunks of 64

__global__ __launch_bounds__(256, 2) void tc_gemm(const float* __restrict__ bsv,
                                                  const float* __restrict__ bgv) {
    extern __shared__ char smem[];
    const uint32_t sbase = smem_u32(smem);
    const int tid  = threadIdx.x;
    const int wid  = tid >> 5, lane = tid & 31;
    const int wm   = wid >> 1;           // 0..3 -> M offset wm*32
    const int wn   = wid & 1;            // 0..1 -> N offset wn*64
    const int ntile = blockIdx.x;        // 0..15
    const int mtile = blockIdx.y;        // 0..255

    const __half* Abase = g_xs + (size_t)mtile * 128 * KX;
    const __half* Bbase = g_ws + (size_t)ntile * 128 * KW;

    float acc[2][8][4];
    #pragma unroll
    for (int g = 0; g < 2; ++g)
        #pragma unroll
        for (int j = 0; j < 8; ++j)
            #pragma unroll
            for (int q = 0; q < 4; ++q) acc[g][j][q] = 0.0f;

    auto issue_loads = [&](int it, int buf) {
        const int kk   = (it & 15) * 64;
        const int acol = ((it >> 4) ? 1024 : 0) + kk;   // seg1 reads x_lo
        const uint32_t sb = sbase + buf * STAGE_BYTES;
        #pragma unroll
        for (int i = 0; i < 4; ++i) {                 // A: 1024 16B-chunks / 256 thr
            int q = tid + i * 256;
            int row = q >> 3, c = q & 7;
            CP_ASYNC16(sb + sw128(row * 128 + c * 16),
                       Abase + (size_t)row * KX + acol + c * 8);
        }
        #pragma unroll
        for (int i = 0; i < 4; ++i) {                 // B: 1024 chunks (W_hi only)
            int q = tid + i * 256;
            int row = q >> 3, c = q & 7;
            CP_ASYNC16(sb + A_BYTES + sw128(row * 128 + c * 16),
                       Bbase + (size_t)row * KW + kk + c * 8);
        }
    };

    issue_loads(0, 0); CP_COMMIT();
    issue_loads(1, 1); CP_COMMIT();

    const uint32_t arow  = (uint32_t)(wm * 32 + (lane & 15)) * 128;
    const uint32_t brow  = (uint32_t)(wn * 64 + (lane & 15)) * 128;
    const uint32_t khalf = ((lane >> 4) & 1) * 16;

    int buf = 0;
    for (int it = 0; it < KITERS; ++it) {
        CP_WAIT(1);
        __syncthreads();
        const int nbuf = (buf + 2 >= NSTAGE) ? buf + 2 - NSTAGE : buf + 2;
        if (it + 2 < KITERS) issue_loads(it + 2, nbuf);
        CP_COMMIT();

        const uint32_t sA = sbase + buf * STAGE_BYTES;
        const uint32_t sB = sA + A_BYTES;

        #pragma unroll
        for (int ks = 0; ks < 4; ++ks) {
            const uint32_t kb = ks * 32 + khalf;
            uint32_t a0[4], a1[4];
            ldsm_x4(a0, sA + sw128(arow + kb));
            ldsm_x4(a1, sA + sw128(arow + 2048 + kb));    // +16 rows
            uint32_t b[4][4];
            #pragma unroll
            for (int q = 0; q < 4; ++q)
                ldsm_x4(b[q], sB + sw128(brow + q * 2048 + kb));
            #pragma unroll
            for (int q = 0; q < 4; ++q) {
                mma16816(acc[0][2 * q + 0], a0, b[q][0], b[q][2]);
                mma16816(acc[0][2 * q + 1], a0, b[q][1], b[q][3]);
                mma16816(acc[1][2 * q + 0], a1, b[q][0], b[q][2]);
                mma16816(acc[1][2 * q + 1], a1, b[q][1], b[q][3]);
            }
        }
        buf = (buf + 1 >= NSTAGE) ? 0 : buf + 1;
    }

    // Epilogue: bias + store fp32 to g_pg
    const int m0 = mtile * 128 + wm * 32 + (lane >> 2);
    const int n0 = ntile * 128 + wn * 64 + 2 * (lane & 3);
    const float* bias = (ntile < 8) ? bsv : bgv;
    const int nb = (ntile < 8) ? n0 : n0 - 1024;

    #pragma unroll
    for (int j = 0; j < 8; ++j) {
        const int col = n0 + j * 8;
        const float bx = __ldg(bias + (nb + j * 8));
        const float by = __ldg(bias + (nb + j * 8) + 1);
        #pragma unroll
        for (int g = 0; g < 2; ++g) {
            const size_t r0 = (size_t)(m0 + g * 16);
            float2 v0 = {acc[g][j][0] + bx, acc[g][j][1] + by};
            float2 v1 = {acc[g][j][2] + bx, acc[g][j][3] + by};
            *(float2*)(g_pg + r0 * N_DIM + col)       = v0;
            *(float2*)(g_pg + (r0 + 8) * N_DIM + col) = v1;
        }
    }
}

// ---------------------------------------------------------------------------
// Sequential scan: s = tanh(p_t + s); out = sigmoid(z_t) * s
// Latency-hiding: 16-deep register ring, loads issued 16 iterations ahead
// (32 outstanding LDGs/thread covers ~577-cyc DRAM latency).
// 256 blocks x 32 threads: one warp per SM(SP), all 148 SMs engaged.
// ---------------------------------------------------------------------------
__device__ __forceinline__ float fast_ex2(float x) {
    float y; asm("ex2.approx.f32 %0, %1;" : "=f"(y) : "f"(x)); return y;
}
__device__ __forceinline__ float fast_rcp(float x) {
    float y; asm("rcp.approx.f32 %0, %1;" : "=f"(y) : "f"(x)); return y;
}

#define SCAN_PF 16   // ring depth (prefetch distance)

__global__ __launch_bounds__(32) void scan_kernel(float* __restrict__ out,
                                                  float* __restrict__ finals) {
    const int gid = blockIdx.x * 32 + threadIdx.x;          // 0..8191
    const int b = gid >> 10;
    const int c = gid & (C_DIM - 1);

    const float* pp = g_pg + (size_t)b * T_DIM * N_DIM + c; // p stream (col c)
    float*       op = out  + (size_t)b * T_DIM * C_DIM + c;

    const float L2E  = 1.4426950408889634f;
    const float L2E2 = 2.8853900817779268f;

    float pr[SCAN_PF], gr[SCAN_PF];
    // Prologue: fill the ring with iters 0..15
    {
        const float* lp = pp;
        #pragma unroll
        for (int j = 0; j < SCAN_PF; ++j) {
            pr[j] = __ldcs(lp);
            gr[j] = __ldcs(lp + C_DIM);
            lp += N_DIM;
        }
    }

    const float* lp = pp + (size_t)SCAN_PF * N_DIM;   // next load position
    float s = 0.0f;

    for (int t = 0; t < T_DIM - SCAN_PF; t += SCAN_PF) {
        #pragma unroll
        for (int j = 0; j < SCAN_PF; ++j) {
            float p  = pr[j];
            float zg = gr[j];
            // refill ring slot j with iteration t+16+j (independent of chain)
            pr[j] = __ldcs(lp);
            gr[j] = __ldcs(lp + C_DIM);
            lp += N_DIM;
            float gate = fast_rcp(1.0f + fast_ex2(-zg * L2E));
            float E = fast_ex2(fmaf(s, L2E2, p * L2E2));
            float r = fast_rcp(1.0f + E);
            s = fmaf(-2.0f, r, 1.0f);
            __stcs(op, gate * s);
            op += C_DIM;
        }
    }
    // Epilogue: drain the last 16 ring entries (no more loads)
    #pragma unroll
    for (int j = 0; j < SCAN_PF; ++j) {
        float p  = pr[j];
        float zg = gr[j];
        float gate = fast_rcp(1.0f + fast_ex2(-zg * L2E));
        float E = fast_ex2(fmaf(s, L2E2, p * L2E2));
        float r = fast_rcp(1.0f + E);
        s = fmaf(-2.0f, r, 1.0f);
        __stcs(op, gate * s);
        op += C_DIM;
    }
    if (finals) finals[gid] = s;
}

// ---------------------------------------------------------------------------
extern "C" void kernel_launch(void* const* d_in, const int* in_sizes, int n_in,
                              void* d_out, int out_size) {
    const float* x  = (const float*)d_in[0];
    const float* Ws = (const float*)d_in[1];
    const float* bs = (const float*)d_in[2];
    const float* Wg = (const float*)d_in[3];
    const float* bg = (const float*)d_in[4];
    float* out = (float*)d_out;

    const size_t btc = (size_t)M_DIM * C_DIM;
    float* finals = ((size_t)out_size >= btc + (size_t)B_DIM * C_DIM)
                        ? out + btc : nullptr;

    cudaFuncSetAttribute(tc_gemm, cudaFuncAttributeMaxDynamicSharedMemorySize,
                         SMEM_TOTAL);

    split_x<<<(M_DIM * C_DIM / 4) / 256, 256>>>(x);
    split_w<<<(N_DIM * C_DIM / 4) / 256, 256>>>(Ws, Wg);
    tc_gemm<<<dim3(16, 256), 256, SMEM_TOTAL>>>(bs, bg);
    scan_kernel<<<B_DIM * C_DIM / 32, 32>>>(out, finals);
}